// round 16
// baseline (speedup 1.0000x reference)
#include <cuda_runtime.h>

// coattention_17738214933118
//
// Mathematical collapse: softmax over a size-1 trailing axis == 1.0, so the
// whole co-attention graph is dead code:
//   out[b, 0:32]  = sum_s X1[b, s, :]
//   out[b, 32:64] = sum_t C [b, t, :]
//
// L2-residency plan (graph is replayed; 128MB working set vs ~126MB L2):
//   pin X1 (64MB) + C batches [0,1024) (16MB) with evict_last  -> 80MB knee
//   stream C batches [1024,4096) (48MB) with evict_first.
// Pin curve (dur_us): 64MB->16.9, 80MB->14.85 (knee), 84/88MB->15.1,
// 104MB->22.3. Other closed lines: high-MLP/low-occ (regressed), no-allocate
// streams (ptxas rejects static forms; fractional cache_hint kills retention).
//
// R15: wave-balance the streamed work. Old mapping clustered all streamed C
// in blocks 256..1023 -> the ~1.7-wave launch ended in a slow all-DRAM wave.
// Remap C slot b -> bc = (b&3)*1024 + (b>>2): every CTA now gets exactly
// 1 pinned + 3 streamed C warps (plus 4 pinned X1 warps), so DRAM and L2
// traffic flow concurrently from every SM. Bijective remap; loads, pin set,
// and coalescing unchanged -- only warp->batch assignment and output index.

static constexpr int BATCH_F4 = 128 * 8;   // 1024 float4 per (batch, tensor)
static constexpr int B_PIN    = 1024;      // C batches pinned in L2 (16 MB)

__device__ __forceinline__ void ld_keep32(const float4* p, float* v) {
    asm volatile(
        "ld.global.nc.L2::evict_last.v8.b32 {%0,%1,%2,%3,%4,%5,%6,%7}, [%8];"
        : "=f"(v[0]), "=f"(v[1]), "=f"(v[2]), "=f"(v[3]),
          "=f"(v[4]), "=f"(v[5]), "=f"(v[6]), "=f"(v[7])
        : "l"(p));
}

__device__ __forceinline__ void ld_stream32(const float4* p, float* v) {
    asm volatile(
        "ld.global.nc.L2::evict_first.v8.b32 {%0,%1,%2,%3,%4,%5,%6,%7}, [%8];"
        : "=f"(v[0]), "=f"(v[1]), "=f"(v[2]), "=f"(v[3]),
          "=f"(v[4]), "=f"(v[5]), "=f"(v[6]), "=f"(v[7])
        : "l"(p));
}

__global__ __launch_bounds__(256)
void coatt_colsum_kernel(const float4* __restrict__ Cin,
                         const float4* __restrict__ X1in,
                         float4* __restrict__ out) {
    const int wid  = threadIdx.x >> 5;
    const int lane = threadIdx.x & 31;
    const int g    = blockIdx.x * 8 + wid;   // 0..8191 segments
    const int slot = g >> 1;
    const int t    = g & 1;                  // 0 -> X1, 1 -> C

    // X1 keeps the identity mapping; C slots are interleaved so each CTA's
    // four C warps hit batches {k, 1024+k, 2048+k, 3072+k} (1 pinned + 3 streamed).
    const int b = (t == 0) ? slot : ((slot & 3) * 1024 + (slot >> 2));

    // 32B chunks: lane handles byte offset 32*lane + 1024*i within its
    // segment -> row = (lane>>2) + 8*i, float cols (lane&3)*8 .. +8.
    float acc[8];
    #pragma unroll
    for (int k = 0; k < 8; ++k) acc[k] = 0.f;

    const float4* base = (t ? Cin : X1in) + (size_t)b * BATCH_F4 + lane * 2;
    const bool keep = (t == 0) || (b < B_PIN);

    if (keep) {
        #pragma unroll
        for (int i = 0; i < 16; ++i) {
            float v[8];
            ld_keep32(base + i * 64, v);
            #pragma unroll
            for (int k = 0; k < 8; ++k) acc[k] += v[k];
        }
    } else {
        #pragma unroll
        for (int i = 0; i < 16; ++i) {
            float v[8];
            ld_stream32(base + i * 64, v);
            #pragma unroll
            for (int k = 0; k < 8; ++k) acc[k] += v[k];
        }
    }

    // Fold the 8 row-residues (lane bits 2,3,4).
    #pragma unroll
    for (int m = 4; m <= 16; m <<= 1) {
        #pragma unroll
        for (int k = 0; k < 8; ++k)
            acc[k] += __shfl_xor_sync(0xffffffffu, acc[k], m);
    }

    if (lane < 4) {
        // out: (B,1,64) fp32 = 16 float4 per batch; X1 sums then C sums.
        float4* o = out + (size_t)b * 16 + t * 8 + lane * 2;
        o[0] = make_float4(acc[0], acc[1], acc[2], acc[3]);
        o[1] = make_float4(acc[4], acc[5], acc[6], acc[7]);
    }
}

extern "C" void kernel_launch(void* const* d_in, const int* in_sizes, int n_in,
                              void* d_out, int out_size) {
    // metadata order: C, X1, W, Ws, Wc, was, wac
    const float4* Cin  = (const float4*)d_in[0];
    const float4* X1in = (const float4*)d_in[1];
    float4* out = (float4*)d_out;
    (void)in_sizes; (void)n_in; (void)out_size;

    coatt_colsum_kernel<<<1024, 256>>>(Cin, X1in, out);
}

// round 17
// speedup vs baseline: 1.0172x; 1.0172x over previous
#include <cuda_runtime.h>

// coattention_17738214933118
//
// Mathematical collapse: softmax over a size-1 trailing axis == 1.0, so the
// whole co-attention graph is dead code:
//   out[b, 0:32]  = sum_s X1[b, s, :]
//   out[b, 32:64] = sum_t C [b, t, :]
//
// L2-residency plan (graph is replayed; 128MB working set vs ~126MB L2):
//   pin X1 (64MB) + C batches [0,1024) (16MB) with evict_last  -> 80MB knee
//   stream C batches [1024,4096) (48MB) with evict_first.
// Pin curve (dur_us): 64MB->16.9, 80MB->14.85 (knee), 84/88MB->15.1,
// 104MB->22.3. Closed lines: high-MLP/low-occ (regressed), no-allocate
// streams (ptxas rejects static forms; fractional cache_hint kills retention),
// streamed-work interleave (neutral/worse).
//
// R16: last unprobed traffic stream -- the output writes. 1MB/replay was
// stored via 2x STG.128 at default (evict_normal) priority, allocating into
// sets that hold pinned lines. Merge into one st.global.L2::evict_first
// .v8.b32 (32B per lane): recyclable lines, minimal pressure on the pin set.

static constexpr int BATCH_F4 = 128 * 8;   // 1024 float4 per (batch, tensor)
static constexpr int B_PIN    = 1024;      // C batches pinned in L2 (16 MB)

__device__ __forceinline__ void ld_keep32(const float4* p, float* v) {
    asm volatile(
        "ld.global.nc.L2::evict_last.v8.b32 {%0,%1,%2,%3,%4,%5,%6,%7}, [%8];"
        : "=f"(v[0]), "=f"(v[1]), "=f"(v[2]), "=f"(v[3]),
          "=f"(v[4]), "=f"(v[5]), "=f"(v[6]), "=f"(v[7])
        : "l"(p));
}

__device__ __forceinline__ void ld_stream32(const float4* p, float* v) {
    asm volatile(
        "ld.global.nc.L2::evict_first.v8.b32 {%0,%1,%2,%3,%4,%5,%6,%7}, [%8];"
        : "=f"(v[0]), "=f"(v[1]), "=f"(v[2]), "=f"(v[3]),
          "=f"(v[4]), "=f"(v[5]), "=f"(v[6]), "=f"(v[7])
        : "l"(p));
}

__device__ __forceinline__ void st_stream32(float4* p, const float* v) {
    asm volatile(
        "st.global.L2::evict_first.v8.b32 [%0], {%1,%2,%3,%4,%5,%6,%7,%8};"
        :: "l"(p),
           "f"(v[0]), "f"(v[1]), "f"(v[2]), "f"(v[3]),
           "f"(v[4]), "f"(v[5]), "f"(v[6]), "f"(v[7])
        : "memory");
}

__global__ __launch_bounds__(256)
void coatt_colsum_kernel(const float4* __restrict__ Cin,
                         const float4* __restrict__ X1in,
                         float4* __restrict__ out) {
    const int wid  = threadIdx.x >> 5;
    const int lane = threadIdx.x & 31;
    const int g    = blockIdx.x * 8 + wid;   // 0..8191 segments
    const int b    = g >> 1;
    const int t    = g & 1;                  // 0 -> X1, 1 -> C

    // 32B chunks: lane handles byte offset 32*lane + 1024*i within its
    // segment -> row = (lane>>2) + 8*i, float cols (lane&3)*8 .. +8.
    float acc[8];
    #pragma unroll
    for (int k = 0; k < 8; ++k) acc[k] = 0.f;

    const float4* base = (t ? Cin : X1in) + (size_t)b * BATCH_F4 + lane * 2;
    const bool keep = (t == 0) || (b < B_PIN);

    if (keep) {
        #pragma unroll
        for (int i = 0; i < 16; ++i) {
            float v[8];
            ld_keep32(base + i * 64, v);
            #pragma unroll
            for (int k = 0; k < 8; ++k) acc[k] += v[k];
        }
    } else {
        #pragma unroll
        for (int i = 0; i < 16; ++i) {
            float v[8];
            ld_stream32(base + i * 64, v);
            #pragma unroll
            for (int k = 0; k < 8; ++k) acc[k] += v[k];
        }
    }

    // Fold the 8 row-residues (lane bits 2,3,4).
    #pragma unroll
    for (int m = 4; m <= 16; m <<= 1) {
        #pragma unroll
        for (int k = 0; k < 8; ++k)
            acc[k] += __shfl_xor_sync(0xffffffffu, acc[k], m);
    }

    if (lane < 4) {
        // out: (B,1,64) fp32 = 16 float4 per batch; X1 sums then C sums.
        // One 32B store per lane, marked recyclable.
        st_stream32(out + (size_t)b * 16 + t * 8 + lane * 2, acc);
    }
}

extern "C" void kernel_launch(void* const* d_in, const int* in_sizes, int n_in,
                              void* d_out, int out_size) {
    // metadata order: C, X1, W, Ws, Wc, was, wac
    const float4* Cin  = (const float4*)d_in[0];
    const float4* X1in = (const float4*)d_in[1];
    float4* out = (float4*)d_out;
    (void)in_sizes; (void)n_in; (void)out_size;

    coatt_colsum_kernel<<<1024, 256>>>(Cin, X1in, out);
}